// round 10
// baseline (speedup 1.0000x reference)
#include <cuda_runtime.h>
#include <cstdint>
#include <cstddef>

// Reverse LSTM: B=128, T=2048, H=512.  out[b,t,:] = h_t (consumes x[b, T-1-t]).
//
// Persistent kernel: 128 CTAs = 4 batch-groups (bg, 32 rows) x 32 col-groups
// (cg, 16 h-cols = 64 z-cols). Wh slice (128KB) SMEM-resident.
// R9: crossbar-lean GEMM. R8 measured L1/LDS crossbar at ~13k cyc/step (the
// true binder; FMA pipe constant at its 8192 floor). New inner loop: 4col x
// 4batch register tile, k-paired FFMA2 (zero packing MOVs): per k-pair
// 2 LDS.128 (w, k-paired layout) + 4 LDS.64 (h, b-major) + 16 FFMA2.
// Crossbar drops 12,288 -> 8,192 cyc/step; issue 7.7k -> 5.6k.
// 512 threads (4 warps/SMSP), 4-way k-split, TMA bulk staging in 2 halves.

#define TT   2048
#define HID  512
#define FPAD 32              // flag padding (uints) -> 128B per flag
#define ZPAD 34              // z exchange row pad (floats), even -> u64 aligned

// [parity][bg][kh][b][256] : each kh-half is a contiguous 32KB TMA source
__device__ float    g_Hbuf[2][4][2][32][256];
__device__ unsigned g_flag[4][32][FPAD];       // [bg][cg][0], padded

typedef unsigned long long u64;

__device__ __forceinline__ void ffma2(u64 &d, u64 a, u64 b) {
    asm volatile("fma.rn.f32x2 %0, %1, %2, %0;" : "+l"(d) : "l"(a), "l"(b));
}
__device__ __forceinline__ float lo32(u64 v) { return __uint_as_float((unsigned)v); }
__device__ __forceinline__ float hi32(u64 v) { return __uint_as_float((unsigned)(v >> 32)); }
__device__ __forceinline__ float fold(u64 v) { return lo32(v) + hi32(v); }

__device__ __forceinline__ void poll_flag(const unsigned* f, unsigned tgt) {
    unsigned v;
    do {
        asm volatile("ld.acquire.gpu.global.u32 %0, [%1];" : "=r"(v) : "l"(f));
    } while (v < tgt);
}
__device__ __forceinline__ void bulk_g2s(unsigned dst_smem, const void* src,
                                         unsigned bytes, unsigned mbar) {
    asm volatile(
        "cp.async.bulk.shared::cluster.global.mbarrier::complete_tx::bytes "
        "[%0], [%1], %2, [%3];"
        :: "r"(dst_smem), "l"(src), "r"(bytes), "r"(mbar) : "memory");
}
__device__ __forceinline__ void mbar_init(unsigned mbar, unsigned cnt) {
    asm volatile("mbarrier.init.shared.b64 [%0], %1;" :: "r"(mbar), "r"(cnt) : "memory");
}
__device__ __forceinline__ void mbar_expect_tx(unsigned mbar, unsigned bytes) {
    asm volatile("mbarrier.arrive.expect_tx.shared.b64 _, [%0], %1;"
                 :: "r"(mbar), "r"(bytes) : "memory");
}
__device__ __forceinline__ void mbar_wait(unsigned mbar, unsigned parity) {
    unsigned done;
    asm volatile(
        "{\n\t.reg .pred p;\n\t"
        "mbarrier.try_wait.parity.acquire.cta.shared::cta.b64 p, [%1], %2;\n\t"
        "selp.b32 %0, 1, 0, p;\n\t}"
        : "=r"(done) : "r"(mbar), "r"(parity) : "memory");
    if (!done) {
        asm volatile(
            "{\n\t.reg .pred P1;\n\t"
            "WL_%=:\n\t"
            "mbarrier.try_wait.parity.acquire.cta.shared::cta.b64 P1, [%0], %1, 0x989680;\n\t"
            "@P1 bra.uni WD_%=;\n\t"
            "bra.uni WL_%=;\n\t"
            "WD_%=:\n\t}"
            :: "r"(mbar), "r"(parity) : "memory");
    }
}

__global__ void lstm_init_kernel() {
    int i = threadIdx.x;                // 128 = 4*32 flags
    g_flag[i >> 5][i & 31][0] = 0u;
}

extern __shared__ float sm[];

__global__ void __launch_bounds__(512, 1)
lstm_persistent_kernel(const float* __restrict__ x,
                       const float* __restrict__ Wi,
                       const float* __restrict__ Wh,
                       const float* __restrict__ bias,
                       float* __restrict__ out)
{
    // SMEM (floats):
    //  WhP [kpg=256][cq=16][ci=4][kk=2] @ 0      (131072 B)  k-paired weights
    //  h_s [kh=2][b=32][256]            @ 32768  ( 65536 B)  b-major per half
    //  z2  [q=4][c=64][ZPAD]            @ 49152  ( 34816 B)
    //  x_s [32]                         @ 57856
    //  mbar u64 x2                      @ 57888  (16B aligned)
    float* WhP = sm;
    float* h_s = sm + 32768;
    float* z2  = sm + 49152;
    float* x_s = sm + 57856;

    const int tid = threadIdx.x;
    const int bg  = blockIdx.x >> 5;     // 0..3
    const int cg  = blockIdx.x & 31;     // 0..31 -> h-cols cg*16..cg*16+15

    const int wid  = tid >> 5;           // 0..15
    const int kq   = wid >> 2;           // k-quarter (k in [kq*128,(kq+1)*128))
    const int ws   = wid & 3;            // col-16-group within tile
    const int lane = tid & 31;
    const int cgrp = lane & 3;           // 4 cols: (ws*4+cgrp)*4 .. +3
    const int bgrp = lane >> 2;          // batches bgrp*4 .. +3
    const int cq   = ws * 4 + cgrp;      // col-quad index 0..15

    const int j = tid & 15;              // gate-phase h-col
    const int b = tid >> 4;              // gate-phase batch row (0..31)

    const unsigned smem_base = (unsigned)__cvta_generic_to_shared(sm);
    const unsigned h_smem    = smem_base + 32768u * 4u;
    const unsigned mbar0     = smem_base + 57888u * 4u;
    const unsigned mbar1     = mbar0 + 8u;

    if (tid == 0) { mbar_init(mbar0, 1); mbar_init(mbar1, 1); }

    // ---- One-time: Wh slice into k-paired layout ----
    // WhP[kpg*128 + cq*8 + ci*2 + kk] = Wh[(kpg*2+kk)*2048 + g*512 + cg*16 + jj]
    // where c = cq*4+ci, g = c>>4, jj = c&15.
    for (int idx = tid; idx < 32768; idx += 512) {
        int kpg = idx >> 7;
        int r   = idx & 127;
        int cqi = r >> 3, ci = (r >> 1) & 3, kk = r & 1;
        int c = cqi * 4 + ci;
        int k = kpg * 2 + kk;
        WhP[idx] = Wh[(size_t)k * 2048 + (c >> 4) * 512 + cg * 16 + (c & 15)];
    }
    float wi_r[4], bi_r[4];
    #pragma unroll
    for (int g = 0; g < 4; ++g) {
        wi_r[g] = Wi[g * 512 + cg * 16 + j];
        bi_r[g] = bias[g * 512 + cg * 16 + j];
    }
    __syncthreads();

    float cst = 0.f;                     // cell state for (b, j)
    const size_t TH = (size_t)TT * HID;

    // GEMM base pointers for this thread's k-quarter
    const float* hp = h_s + (kq >> 1) * 8192 + bgrp * 4 * 256 + (kq & 1) * 128;
    const float* wp = WhP + kq * 8192 + cq * 8;     // stride 128 per k-pair
    const unsigned my_mbar = (kq < 2) ? mbar0 : mbar1;

    for (int t = 0; t < TT; ++t) {
        // x for this step (warp 1; consumed after the z2 syncthreads)
        if (tid >= 32 && tid < 64)
            x_s[tid - 32] = x[(size_t)(bg * 32 + (tid - 32)) * TT + (TT - 1 - t)];

        const unsigned ph = (unsigned)((t + 1) & 1);

        if (t > 0) {
            const unsigned tgt = (unsigned)t;
            // warp 0: lanes 0-15 gate half0 (cols<256 <- producers cg 0..15),
            //         lanes 16-31 gate half1 (cols>=256 <- producers cg 16..31)
            if (tid < 16) {
                poll_flag(&g_flag[bg][tid][0], tgt);
                __syncwarp(0x0000FFFFu);
                if (tid == 0) {
                    mbar_expect_tx(mbar0, 32768u);
                    bulk_g2s(h_smem, &g_Hbuf[t & 1][bg][0][0][0], 32768u, mbar0);
                }
            } else if (tid < 32) {
                poll_flag(&g_flag[bg][tid][0], tgt);
                __syncwarp(0xFFFF0000u);
                if (tid == 16) {
                    mbar_expect_tx(mbar1, 32768u);
                    bulk_g2s(h_smem + 32768u, &g_Hbuf[t & 1][bg][1][0][0], 32768u, mbar1);
                }
            }
            mbar_wait(my_mbar, ph);      // each k-half waits only its own data
        }

        // ---- GEMM: my k-quarter (64 k-pairs), 4col x 4batch, zero packs ----
        u64 a00=0,a01=0,a02=0,a03=0;   // col0, batches 0..3 (each: even/odd k)
        u64 a10=0,a11=0,a12=0,a13=0;
        u64 a20=0,a21=0,a22=0,a23=0;
        u64 a30=0,a31=0,a32=0,a33=0;
        if (t > 0) {
            #pragma unroll 4
            for (int kp = 0; kp < 64; ++kp) {
                ulonglong2 wA = *(const ulonglong2*)(wp + kp * 128);      // c0,c1
                ulonglong2 wB = *(const ulonglong2*)(wp + kp * 128 + 4);  // c2,c3
                u64 h0 = *(const u64*)(hp + kp * 2);
                u64 h1 = *(const u64*)(hp + 256 + kp * 2);
                u64 h2 = *(const u64*)(hp + 512 + kp * 2);
                u64 h3 = *(const u64*)(hp + 768 + kp * 2);
                ffma2(a00, h0, wA.x); ffma2(a01, h1, wA.x);
                ffma2(a02, h2, wA.x); ffma2(a03, h3, wA.x);
                ffma2(a10, h0, wA.y); ffma2(a11, h1, wA.y);
                ffma2(a12, h2, wA.y); ffma2(a13, h3, wA.y);
                ffma2(a20, h0, wB.x); ffma2(a21, h1, wB.x);
                ffma2(a22, h2, wB.x); ffma2(a23, h3, wB.x);
                ffma2(a30, h0, wB.y); ffma2(a31, h1, wB.y);
                ffma2(a32, h2, wB.y); ffma2(a33, h3, wB.y);
            }
        }

        // ---- fold k-pairs, scatter partial z: z2[kq][c][b] ----
        {
            float* zp = z2 + kq * 64 * ZPAD + bgrp * 4;
            float2 v;
            float* p;
            p = zp + (cq * 4 + 0) * ZPAD;
            v = make_float2(fold(a00), fold(a01)); *(float2*)p = v;
            v = make_float2(fold(a02), fold(a03)); *(float2*)(p + 2) = v;
            p = zp + (cq * 4 + 1) * ZPAD;
            v = make_float2(fold(a10), fold(a11)); *(float2*)p = v;
            v = make_float2(fold(a12), fold(a13)); *(float2*)(p + 2) = v;
            p = zp + (cq * 4 + 2) * ZPAD;
            v = make_float2(fold(a20), fold(a21)); *(float2*)p = v;
            v = make_float2(fold(a22), fold(a23)); *(float2*)(p + 2) = v;
            p = zp + (cq * 4 + 3) * ZPAD;
            v = make_float2(fold(a30), fold(a31)); *(float2*)p = v;
            v = make_float2(fold(a32), fold(a33)); *(float2*)(p + 2) = v;
        }
        __syncthreads();

        // ---- gates: fold 4 k-quarters, 1 output per thread ----
        {
            float zg_[4];
            #pragma unroll
            for (int g = 0; g < 4; ++g) {
                int c = g * 16 + j;
                zg_[g] = (z2[c * ZPAD + b]              + z2[64 * ZPAD + c * ZPAD + b])
                       + (z2[128 * ZPAD + c * ZPAD + b] + z2[192 * ZPAD + c * ZPAD + b]);
            }
            float xr = x_s[b];
            float vi = zg_[0] + xr * wi_r[0] + bi_r[0];
            float vf = zg_[1] + xr * wi_r[1] + bi_r[1];
            float vg = zg_[2] + xr * wi_r[2] + bi_r[2];
            float vo = zg_[3] + xr * wi_r[3] + bi_r[3];
            float ig = 1.0f / (1.0f + __expf(-vi));
            float fg = 1.0f / (1.0f + __expf(-vf));
            float eg = __expf(2.0f * vg);
            float gv = 1.0f - 2.0f / (eg + 1.0f);          // tanh(vg)
            float og = 1.0f / (1.0f + __expf(-vo));
            float cn = fg * cst + ig * gv;
            cst = cn;
            float ec = __expf(2.0f * cn);
            float hr = og * (1.0f - 2.0f / (ec + 1.0f));   // o * tanh(c)

            out[(size_t)(bg * 32 + b) * TH + (size_t)t * HID + cg * 16 + j] = hr;
            // publish in [kh][b][256] layout for next step's bulk staging
            int col = cg * 16 + j;
            g_Hbuf[(t + 1) & 1][bg][col >> 8][b][col & 255] = hr;
        }

        // ---- release: st.release (cumulative) publishes all CTA h writes ----
        __syncthreads();
        if (tid == 0) {
            asm volatile("st.release.gpu.global.u32 [%0], %1;"
                         :: "l"(&g_flag[bg][cg][0]), "r"((unsigned)(t + 1))
                         : "memory");
        }
    }
}

extern "C" void kernel_launch(void* const* d_in, const int* in_sizes, int n_in,
                              void* d_out, int out_size)
{
    // inputs: [0]=s (unused), [1]=x (128*2048), [2]=Wi (2048), [3]=Wh (512*2048), [4]=b (2048)
    const float* x    = (const float*)d_in[1];
    const float* Wi   = (const float*)d_in[2];
    const float* Wh   = (const float*)d_in[3];
    const float* bias = (const float*)d_in[4];
    float* out = (float*)d_out;

    size_t smem = (size_t)(57888 + 4) * sizeof(float);   // 231568 B
    cudaFuncSetAttribute(lstm_persistent_kernel,
                         cudaFuncAttributeMaxDynamicSharedMemorySize, (int)smem);

    lstm_init_kernel<<<1, 128>>>();
    lstm_persistent_kernel<<<128, 512, smem>>>(x, Wi, Wh, bias, out);
}

// round 11
// speedup vs baseline: 1.8200x; 1.8200x over previous
#include <cuda_runtime.h>
#include <cstdint>
#include <cstddef>

// Reverse LSTM: B=128, T=2048, H=512.  out[b,t,:] = h_t (consumes x[b, T-1-t]).
//
// Persistent kernel: 128 CTAs = 4 batch-groups (bg, 32 rows) x 32 col-groups
// (cg, 16 h-cols = 64 z-cols). Wh slice (128KB) SMEM-resident.
// R10: NO staging. The step preamble (poll -> 32KB TMA -> mbar -> sync) was
// ~4-6k exposed cycles in R2-R9; h is L2-resident (64KB/bg), so the GEMM now
// streams it directly with ld.global.cg broadcast loads that pipeline into
// the FFMA2s like a normal L2 GEMM mainloop. L1 bypass (.cg) is required:
// parity buffers alternate and L1 would hold stale lines from step t-2.
// 512 threads = 4 warps/SMSP; warp = (k-quarter, batch-octet); per-lane flag
// polls (8 producers per k-quarter), z folded via padded SMEM exchange.

#define TT   2048
#define HID  512
#define FPAD 32              // flag padding (uints) -> 128B per flag
#define ZPAD 34              // z exchange row pad (floats), even -> u64 aligned

__device__ float    g_Hbuf[2][4][HID * 32];    // [parity][bg][k*32 + b]  k-major
__device__ unsigned g_flag[4][32][FPAD];       // [bg][cg][0], padded

typedef unsigned long long u64;

__device__ __forceinline__ void ffma2(u64 &d, u64 a, u64 b) {
    asm volatile("fma.rn.f32x2 %0, %1, %2, %0;" : "+l"(d) : "l"(a), "l"(b));
}
__device__ __forceinline__ u64 pack2(float x) {
    u64 r; asm("mov.b64 %0, {%1, %1};" : "=l"(r) : "f"(x)); return r;
}

// 16B L2-only load (L1 bypass), two f32x2-ready u64 halves
__device__ __forceinline__ ulonglong2 ldg_cg16(const float* p) {
    ulonglong2 r;
    asm volatile("ld.global.cg.v2.b64 {%0, %1}, [%2];"
                 : "=l"(r.x), "=l"(r.y) : "l"(p));
    return r;
}
__device__ __forceinline__ void poll_flag(const unsigned* f, unsigned tgt) {
    unsigned v;
    do {
        asm volatile("ld.acquire.gpu.global.u32 %0, [%1];"
                     : "=r"(v) : "l"(f) : "memory");
    } while (v < tgt);
}

__global__ void lstm_init_kernel() {
    int i = threadIdx.x;                // 128 = 4*32 flags
    g_flag[i >> 5][i & 31][0] = 0u;
}

extern __shared__ float sm[];

__global__ void __launch_bounds__(512, 1)
lstm_persistent_kernel(const float* __restrict__ x,
                       const float* __restrict__ Wi,
                       const float* __restrict__ Wh,
                       const float* __restrict__ bias,
                       float* __restrict__ out)
{
    // SMEM (floats):
    //  Wh_s [k=512][c=64]     @ 0      (131072 B)   c = g*16 + j
    //  z2   [q=4][c=64][ZPAD] @ 32768  ( 34816 B)
    //  x_s  [32]              @ 41472            total 166,016 B
    float* Wh_s = sm;
    float* z2   = sm + 32768;
    float* x_s  = sm + 41472;

    const int tid = threadIdx.x;
    const int bg  = blockIdx.x >> 5;     // 0..3
    const int cg  = blockIdx.x & 31;     // 0..31 -> h-cols cg*16..cg*16+15

    const int wid  = tid >> 5;           // 0..15
    const int kq   = wid >> 2;           // k-quarter (k in [kq*128,(kq+1)*128))
    const int oct  = wid & 3;            // batch octet (b = oct*8 .. oct*8+7)
    const int lane = tid & 31;           // col-pair (cols 2*lane, 2*lane+1)

    const int j = tid & 15;              // gate-phase h-col
    const int b = tid >> 4;              // gate-phase batch row (0..31)

    // ---- One-time: Wh slice (col c = g*16+j <-> global g*512 + cg*16 + j) ----
    for (int idx = tid; idx < HID * 64; idx += 512) {
        int k = idx >> 6, c = idx & 63;
        Wh_s[idx] = Wh[(size_t)k * 2048 + (c >> 4) * 512 + cg * 16 + (c & 15)];
    }
    float wi_r[4], bi_r[4];
    #pragma unroll
    for (int g = 0; g < 4; ++g) {
        wi_r[g] = Wi[g * 512 + cg * 16 + j];
        bi_r[g] = bias[g * 512 + cg * 16 + j];
    }
    __syncthreads();

    float cst = 0.f;                     // cell state for (b, j)
    const size_t TH = (size_t)TT * HID;

    const float*    wp    = Wh_s + kq * 8192 + lane * 2;
    const unsigned* myflg = &g_flag[bg][kq * 8 + (lane & 7)][0];

    for (int t = 0; t < TT; ++t) {
        // x for this step (consumed by gates after the z2 syncthreads)
        if (tid < 32)
            x_s[tid] = x[(size_t)(bg * 32 + tid) * TT + (TT - 1 - t)];

        u64 a00 = 0, a01 = 0, a02 = 0, a03 = 0;   // col0, b-pairs 0..3 of octet
        u64 a10 = 0, a11 = 0, a12 = 0, a13 = 0;   // col1

        if (t > 0) {
            // acquire: lanes 0-7 poll this k-quarter's 8 producer flags
            // (released at the end of the producers' step t-1 -> ready in
            // steady state; one ~L2-latency read each, MLP-overlapped)
            if (lane < 8) poll_flag(myflg, (unsigned)t);
            __syncwarp();

            const float* hgp = &g_Hbuf[t & 1][bg][0] + kq * 4096 + oct * 8;
            #pragma unroll 8
            for (int kk = 0; kk < 128; ++kk) {
                ulonglong2 hA = ldg_cg16(hgp + kk * 32);      // b0..b3 (broadcast)
                ulonglong2 hB = ldg_cg16(hgp + kk * 32 + 4);  // b4..b7 (broadcast)
                float2 w = *(const float2*)(wp + kk * 64);    // LDS, conflict-free
                u64 W0 = pack2(w.x), W1 = pack2(w.y);
                ffma2(a00, hA.x, W0); ffma2(a01, hA.y, W0);
                ffma2(a02, hB.x, W0); ffma2(a03, hB.y, W0);
                ffma2(a10, hA.x, W1); ffma2(a11, hA.y, W1);
                ffma2(a12, hB.x, W1); ffma2(a13, hB.y, W1);
            }
        }

        // ---- scatter partial z: z2[kq][c][b] ----
        {
            float* zp = z2 + kq * 64 * ZPAD;
            int cc = 2 * lane;
            float* p0 = zp + cc * ZPAD + oct * 8;
            float* p1 = zp + (cc + 1) * ZPAD + oct * 8;
            *(u64*)(p0 + 0) = a00; *(u64*)(p0 + 2) = a01;
            *(u64*)(p0 + 4) = a02; *(u64*)(p0 + 6) = a03;
            *(u64*)(p1 + 0) = a10; *(u64*)(p1 + 2) = a11;
            *(u64*)(p1 + 4) = a12; *(u64*)(p1 + 6) = a13;
        }
        __syncthreads();

        // ---- gates: fold 4 k-quarters, 1 output per thread ----
        {
            float zg_[4];
            #pragma unroll
            for (int g = 0; g < 4; ++g) {
                int c = g * 16 + j;
                zg_[g] = (z2[c * ZPAD + b]              + z2[64 * ZPAD + c * ZPAD + b])
                       + (z2[128 * ZPAD + c * ZPAD + b] + z2[192 * ZPAD + c * ZPAD + b]);
            }
            float xr = x_s[b];
            float vi = zg_[0] + xr * wi_r[0] + bi_r[0];
            float vf = zg_[1] + xr * wi_r[1] + bi_r[1];
            float vg = zg_[2] + xr * wi_r[2] + bi_r[2];
            float vo = zg_[3] + xr * wi_r[3] + bi_r[3];
            float ig = 1.0f / (1.0f + __expf(-vi));
            float fg = 1.0f / (1.0f + __expf(-vf));
            float eg = __expf(2.0f * vg);
            float gv = 1.0f - 2.0f / (eg + 1.0f);          // tanh(vg)
            float og = 1.0f / (1.0f + __expf(-vo));
            float cn = fg * cst + ig * gv;
            cst = cn;
            float ec = __expf(2.0f * cn);
            float hr = og * (1.0f - 2.0f / (ec + 1.0f));   // o * tanh(c)

            out[(size_t)(bg * 32 + b) * TH + (size_t)t * HID + cg * 16 + j] = hr;
            // k-major publish for next step's streaming loads
            g_Hbuf[(t + 1) & 1][bg][(cg * 16 + j) * 32 + b] = hr;
        }

        // ---- release: cumulative st.release publishes this CTA's h writes ----
        __syncthreads();
        if (tid == 0) {
            asm volatile("st.release.gpu.global.u32 [%0], %1;"
                         :: "l"(&g_flag[bg][cg][0]), "r"((unsigned)(t + 1))
                         : "memory");
        }
    }
}

extern "C" void kernel_launch(void* const* d_in, const int* in_sizes, int n_in,
                              void* d_out, int out_size)
{
    // inputs: [0]=s (unused), [1]=x (128*2048), [2]=Wi (2048), [3]=Wh (512*2048), [4]=b (2048)
    const float* x    = (const float*)d_in[1];
    const float* Wi   = (const float*)d_in[2];
    const float* Wh   = (const float*)d_in[3];
    const float* bias = (const float*)d_in[4];
    float* out = (float*)d_out;

    size_t smem = (size_t)(41472 + 32) * sizeof(float);   // 166,016 B
    cudaFuncSetAttribute(lstm_persistent_kernel,
                         cudaFuncAttributeMaxDynamicSharedMemorySize, (int)smem);

    lstm_init_kernel<<<1, 128>>>();
    lstm_persistent_kernel<<<128, 512, smem>>>(x, Wi, Wh, bias, out);
}

// round 12
// speedup vs baseline: 2.2313x; 1.2260x over previous
#include <cuda_runtime.h>
#include <cstdint>
#include <cstddef>

// Reverse LSTM: B=128, T=2048, H=512.  out[b,t,:] = h_t (consumes x[b, T-1-t]).
//
// Persistent kernel: 128 CTAs = 4 batch-groups (bg, 32 rows) x 32 col-groups
// (cg, 16 h-cols = 64 z-cols). Wh slice (128KB) SMEM-resident.
// R11: fat-wavefront GEMM. L1TEX wavefronts were a co-binder in every round
// (skinny 16B broadcast LDS). New tile: warp = 32c x 32b, thread = 4c x 8b.
// Per k per warp: 1 full-128B w LDS.128 + 2 h LDS.128 (64B/wf) = 3 wf
// (was 4 with only 8 FFMA2), 16 FFMA2, 27 issues. 256 threads = 8 warps =
// 2/SMSP: issue/SMSP 6912 < pipe 8192 -> FMA-bound with slack. L1TEX/step
// drops 8192 -> ~3k wf. Sync skeleton from R8 (flags + 2-half TMA + mbars).

#define TT   2048
#define HID  512
#define FPAD 32              // flag padding (uints) -> 128B per flag
#define ZPAD 34              // z exchange row pad (floats)

__device__ float    g_Hbuf[2][4][HID * 32];    // [parity][bg][k*32 + b]  k-major
__device__ unsigned g_flag[4][32][FPAD];       // [bg][cg][0], padded

typedef unsigned long long u64;

__device__ __forceinline__ void ffma2(u64 &d, u64 a, u64 b) {
    asm volatile("fma.rn.f32x2 %0, %1, %2, %0;" : "+l"(d) : "l"(a), "l"(b));
}
__device__ __forceinline__ u64 pack2(float x) {
    u64 r; asm("mov.b64 %0, {%1, %1};" : "=l"(r) : "f"(x)); return r;
}
__device__ __forceinline__ float lo32(u64 v) { return __uint_as_float((unsigned)v); }
__device__ __forceinline__ float hi32(u64 v) { return __uint_as_float((unsigned)(v >> 32)); }

__device__ __forceinline__ void poll_flag(const unsigned* f, unsigned tgt) {
    unsigned v;
    do {
        asm volatile("ld.acquire.gpu.global.u32 %0, [%1];"
                     : "=r"(v) : "l"(f) : "memory");
    } while (v < tgt);
}
__device__ __forceinline__ void bulk_g2s(unsigned dst_smem, const void* src,
                                         unsigned bytes, unsigned mbar) {
    asm volatile(
        "cp.async.bulk.shared::cluster.global.mbarrier::complete_tx::bytes "
        "[%0], [%1], %2, [%3];"
        :: "r"(dst_smem), "l"(src), "r"(bytes), "r"(mbar) : "memory");
}
__device__ __forceinline__ void mbar_init(unsigned mbar, unsigned cnt) {
    asm volatile("mbarrier.init.shared.b64 [%0], %1;" :: "r"(mbar), "r"(cnt) : "memory");
}
__device__ __forceinline__ void mbar_expect_tx(unsigned mbar, unsigned bytes) {
    asm volatile("mbarrier.arrive.expect_tx.shared.b64 _, [%0], %1;"
                 :: "r"(mbar), "r"(bytes) : "memory");
}
__device__ __forceinline__ void mbar_wait(unsigned mbar, unsigned parity) {
    unsigned done;
    asm volatile(
        "{\n\t.reg .pred p;\n\t"
        "mbarrier.try_wait.parity.acquire.cta.shared::cta.b64 p, [%1], %2;\n\t"
        "selp.b32 %0, 1, 0, p;\n\t}"
        : "=r"(done) : "r"(mbar), "r"(parity) : "memory");
    if (!done) {
        asm volatile(
            "{\n\t.reg .pred P1;\n\t"
            "WL_%=:\n\t"
            "mbarrier.try_wait.parity.acquire.cta.shared::cta.b64 P1, [%0], %1, 0x989680;\n\t"
            "@P1 bra.uni WD_%=;\n\t"
            "bra.uni WL_%=;\n\t"
            "WD_%=:\n\t}"
            :: "r"(mbar), "r"(parity) : "memory");
    }
}

__global__ void lstm_init_kernel() {
    int i = threadIdx.x;                // 128 = 4*32 flags
    g_flag[i >> 5][i & 31][0] = 0u;
}

extern __shared__ float sm[];

__global__ void __launch_bounds__(256, 1)
lstm_persistent_kernel(const float* __restrict__ x,
                       const float* __restrict__ Wi,
                       const float* __restrict__ Wh,
                       const float* __restrict__ bias,
                       float* __restrict__ out)
{
    // SMEM (floats):
    //  Wh_s [k=512][c=64]     @ 0      (131072 B)   c = g*16 + j
    //  h_s  [k=512][b=32]     @ 32768  ( 65536 B)   k-major
    //  z2   [q=4][c=64][ZPAD] @ 49152  ( 34816 B)
    //  x_s  [32]              @ 57856
    //  mbar u64 x2            @ 57888  (16B aligned)   total 231,616 B
    float* Wh_s = sm;
    float* h_s  = sm + 32768;
    float* z2   = sm + 49152;
    float* x_s  = sm + 57856;

    const int tid = threadIdx.x;
    const int bg  = blockIdx.x >> 5;     // 0..3
    const int cg  = blockIdx.x & 31;     // 0..31 -> h-cols cg*16..cg*16+15

    const int wid   = tid >> 5;          // 0..7
    const int kq    = wid >> 1;          // k-quarter (k in [kq*128,(kq+1)*128))
    const int chalf = wid & 1;           // column half (32 cols)
    const int lane  = tid & 31;
    const int cgrp  = lane & 7;          // 4 cols: c0 = chalf*32 + cgrp*4
    const int bgrp  = lane >> 3;         // 8 batches: b0 = bgrp*8
    const int c0    = chalf * 32 + cgrp * 4;
    const int b0    = bgrp * 8;

    const int j  = tid & 15;             // gate-phase h-col
    const int b2 = tid >> 4;             // gate-phase batch (b2 and b2+16)

    const unsigned smem_base = (unsigned)__cvta_generic_to_shared(sm);
    const unsigned h_smem    = smem_base + 32768u * 4u;
    const unsigned mbar0     = smem_base + 57888u * 4u;
    const unsigned mbar1     = mbar0 + 8u;

    if (tid == 0) { mbar_init(mbar0, 1); mbar_init(mbar1, 1); }

    // ---- One-time: Wh slice (col c = g*16+j <-> global g*512 + cg*16 + j) ----
    for (int idx = tid; idx < HID * 64; idx += 256) {
        int k = idx >> 6, c = idx & 63;
        Wh_s[idx] = Wh[(size_t)k * 2048 + (c >> 4) * 512 + cg * 16 + (c & 15)];
    }
    float wi_r[4], bi_r[4];
    #pragma unroll
    for (int g = 0; g < 4; ++g) {
        wi_r[g] = Wi[g * 512 + cg * 16 + j];
        bi_r[g] = bias[g * 512 + cg * 16 + j];
    }
    __syncthreads();

    float cstA = 0.f, cstB = 0.f;        // cell state for (b2, j) and (b2+16, j)
    const size_t TH = (size_t)TT * HID;

    const float* hp = h_s  + b0;
    const float* wp = Wh_s + c0;
    const unsigned my_mbar = (kq < 2) ? mbar0 : mbar1;

    for (int t = 0; t < TT; ++t) {
        // x for this step (warp 1; consumed after the z2 syncthreads)
        if (tid >= 32 && tid < 64)
            x_s[tid - 32] = x[(size_t)(bg * 32 + (tid - 32)) * TT + (TT - 1 - t)];

        const unsigned ph = (unsigned)((t + 1) & 1);

        if (t > 0) {
            const unsigned tgt = (unsigned)t;
            // warp 0: lanes 0-15 gate half0 (k<256 <- producers cg 0..15),
            //         lanes 16-31 gate half1 (k>=256 <- producers cg 16..31)
            if (tid < 16) {
                poll_flag(&g_flag[bg][tid][0], tgt);
                __syncwarp(0x0000FFFFu);
                if (tid == 0) {
                    mbar_expect_tx(mbar0, 32768u);
                    bulk_g2s(h_smem, &g_Hbuf[t & 1][bg][0], 32768u, mbar0);
                }
            } else if (tid < 32) {
                poll_flag(&g_flag[bg][tid][0], tgt);
                __syncwarp(0xFFFF0000u);
                if (tid == 16) {
                    mbar_expect_tx(mbar1, 32768u);
                    bulk_g2s(h_smem + 32768u, &g_Hbuf[t & 1][bg][0] + 8192, 32768u, mbar1);
                }
            }
            mbar_wait(my_mbar, ph);      // each k-half waits only its own data
        }

        // ---- GEMM: my k-quarter (128 k), 4col x 8batch, fat wavefronts ----
        // acc[ci][bp]: u64 = z for batches (2bp, 2bp+1) of col c0+ci
        u64 a00=0,a01=0,a02=0,a03=0;
        u64 a10=0,a11=0,a12=0,a13=0;
        u64 a20=0,a21=0,a22=0,a23=0;
        u64 a30=0,a31=0,a32=0,a33=0;
        if (t > 0) {
            const float* hq = hp + kq * 4096;
            const float* wq = wp + kq * 8192;
            #pragma unroll 4
            for (int kk = 0; kk < 128; ++kk) {
                ulonglong2 hA = *(const ulonglong2*)(hq + kk * 32);      // b0..b3
                ulonglong2 hB = *(const ulonglong2*)(hq + kk * 32 + 4);  // b4..b7
                float4 w4 = *(const float4*)(wq + kk * 64);              // 4 cols
                u64 W0 = pack2(w4.x), W1 = pack2(w4.y);
                u64 W2 = pack2(w4.z), W3 = pack2(w4.w);
                ffma2(a00, hA.x, W0); ffma2(a01, hA.y, W0);
                ffma2(a02, hB.x, W0); ffma2(a03, hB.y, W0);
                ffma2(a10, hA.x, W1); ffma2(a11, hA.y, W1);
                ffma2(a12, hB.x, W1); ffma2(a13, hB.y, W1);
                ffma2(a20, hA.x, W2); ffma2(a21, hA.y, W2);
                ffma2(a22, hB.x, W2); ffma2(a23, hB.y, W2);
                ffma2(a30, hA.x, W3); ffma2(a31, hA.y, W3);
                ffma2(a32, hB.x, W3); ffma2(a33, hB.y, W3);
            }
        }

        // ---- scatter partial z: z2[kq][c][b], u64 stores (8B aligned) ----
        {
            float* zp = z2 + kq * 64 * ZPAD + b0;
            float* p;
            p = zp + (c0 + 0) * ZPAD;
            *(u64*)(p) = a00; *(u64*)(p + 2) = a01;
            *(u64*)(p + 4) = a02; *(u64*)(p + 6) = a03;
            p = zp + (c0 + 1) * ZPAD;
            *(u64*)(p) = a10; *(u64*)(p + 2) = a11;
            *(u64*)(p + 4) = a12; *(u64*)(p + 6) = a13;
            p = zp + (c0 + 2) * ZPAD;
            *(u64*)(p) = a20; *(u64*)(p + 2) = a21;
            *(u64*)(p + 4) = a22; *(u64*)(p + 6) = a23;
            p = zp + (c0 + 3) * ZPAD;
            *(u64*)(p) = a30; *(u64*)(p + 2) = a31;
            *(u64*)(p + 4) = a32; *(u64*)(p + 6) = a33;
        }
        __syncthreads();

        // ---- gates: fold 4 k-quarters, 2 outputs per thread (b2, b2+16) ----
        {
            float* hnb = &g_Hbuf[(t + 1) & 1][bg][0];
            #pragma unroll
            for (int r = 0; r < 2; ++r) {
                int b = b2 + r * 16;
                float zg_[4];
                #pragma unroll
                for (int g = 0; g < 4; ++g) {
                    int c = g * 16 + j;
                    zg_[g] = (z2[c * ZPAD + b]              + z2[64 * ZPAD + c * ZPAD + b])
                           + (z2[128 * ZPAD + c * ZPAD + b] + z2[192 * ZPAD + c * ZPAD + b]);
                }
                float xr = x_s[b];
                float vi = zg_[0] + xr * wi_r[0] + bi_r[0];
                float vf = zg_[1] + xr * wi_r[1] + bi_r[1];
                float vg = zg_[2] + xr * wi_r[2] + bi_r[2];
                float vo = zg_[3] + xr * wi_r[3] + bi_r[3];
                float ig = 1.0f / (1.0f + __expf(-vi));
                float fg = 1.0f / (1.0f + __expf(-vf));
                float eg = __expf(2.0f * vg);
                float gv = 1.0f - 2.0f / (eg + 1.0f);          // tanh(vg)
                float og = 1.0f / (1.0f + __expf(-vo));
                float cp = r ? cstB : cstA;
                float cn = fg * cp + ig * gv;
                if (r) cstB = cn; else cstA = cn;
                float ec = __expf(2.0f * cn);
                float hr = og * (1.0f - 2.0f / (ec + 1.0f));   // o * tanh(c)

                out[(size_t)(bg * 32 + b) * TH + (size_t)t * HID + cg * 16 + j] = hr;
                // k-major publish for next step's bulk staging
                hnb[(cg * 16 + j) * 32 + b] = hr;
            }
        }

        // ---- release: cumulative st.release publishes this CTA's h writes ----
        __syncthreads();
        if (tid == 0) {
            asm volatile("st.release.gpu.global.u32 [%0], %1;"
                         :: "l"(&g_flag[bg][cg][0]), "r"((unsigned)(t + 1))
                         : "memory");
        }
    }
}

extern "C" void kernel_launch(void* const* d_in, const int* in_sizes, int n_in,
                              void* d_out, int out_size)
{
    // inputs: [0]=s (unused), [1]=x (128*2048), [2]=Wi (2048), [3]=Wh (512*2048), [4]=b (2048)
    const float* x    = (const float*)d_in[1];
    const float* Wi   = (const float*)d_in[2];
    const float* Wh   = (const float*)d_in[3];
    const float* bias = (const float*)d_in[4];
    float* out = (float*)d_out;

    size_t smem = (size_t)(57888 + 4) * sizeof(float);   // 231,568 B
    cudaFuncSetAttribute(lstm_persistent_kernel,
                         cudaFuncAttributeMaxDynamicSharedMemorySize, (int)smem);

    lstm_init_kernel<<<1, 128>>>();
    lstm_persistent_kernel<<<128, 256, smem>>>(x, Wi, Wh, bias, out);
}